// round 8
// baseline (speedup 1.0000x reference)
#include <cuda_runtime.h>
#include <cuda_bf16.h>
#include <cstdint>

typedef uint32_t u32;

#define HN 50
#define TN 512
#define EN 16
#define NCTA 128
#define NTHR 416   // 13 warps

#define BROW 272
#define BT8  (8*BROW)          // 2176, one 8-row tile
// B tiles: [group][hi,lo] single-buffered, 8 rows x 272B
#define SM_B     0             // 4 * 2176 = 8704
#define SM_A1LO  8704          // [208][272]  = 56576
#define SM_G     65280         // 4 arrays [208][10] f32 = 33280
#define SM_BIAS0 98560
#define SM_BIAS1 99360
#define SM_WL    100160
#define SMEM_BYTES 100480

__device__ __forceinline__ u32 smem_u32(const void* p){
    u32 a; asm("{ .reg .u64 t; cvta.to.shared.u64 t, %1; cvt.u32.u64 %0, t; }" : "=r"(a) : "l"(p));
    return a;
}
__device__ __forceinline__ u32 pk2bf(__nv_bfloat16 a, __nv_bfloat16 b){
    return (u32)__bfloat16_as_ushort(a) | ((u32)__bfloat16_as_ushort(b) << 16);
}
__device__ __forceinline__ void mma_bf16(float* c, const u32* a, u32 b0, u32 b1){
    asm volatile("mma.sync.aligned.m16n8k16.row.col.f32.bf16.bf16.f32 "
                 "{%0,%1,%2,%3}, {%4,%5,%6,%7}, {%8,%9}, {%0,%1,%2,%3};"
                 : "+f"(c[0]), "+f"(c[1]), "+f"(c[2]), "+f"(c[3])
                 : "r"(a[0]), "r"(a[1]), "r"(a[2]), "r"(a[3]), "r"(b0), "r"(b1));
}
__device__ __forceinline__ void ldsm4(u32* r, u32 addr){
    asm volatile("ldmatrix.sync.aligned.m8n8.x4.shared.b16 {%0,%1,%2,%3}, [%4];"
                 : "=r"(r[0]), "=r"(r[1]), "=r"(r[2]), "=r"(r[3]) : "r"(addr));
}
__device__ __forceinline__ void ldsm2(u32* r, u32 addr){
    asm volatile("ldmatrix.sync.aligned.m8n8.x2.shared.b16 {%0,%1}, [%2];"
                 : "=r"(r[0]), "=r"(r[1]) : "r"(addr));
}
__device__ __forceinline__ float sigf(float v){
    return __fdividef(1.f, 1.f + __expf(-v));
}
__device__ __forceinline__ float tanhx(float v){
    return fmaf(2.f, __fdividef(1.f, 1.f + __expf(-2.f * v)), -1.f);
}

// unified K layout: cols 0-7 = x, 8-57 = h0, 58-107 = h1, 108-111 pad
__device__ __forceinline__ float a0elem(int g, int k, const float* Whh0, const float* Wih0){
    if (g >= 200) return 0.f;
    if (k < 8)  return Wih0[g * 8 + k];
    if (k < 58) return Whh0[g * 50 + (k - 8)];
    return 0.f;
}
__device__ __forceinline__ float a1elem(int g, int k, const float* Wih1, const float* Whh1){
    if (g >= 200) return 0.f;
    if (k >= 8  && k < 58)  return Wih1[g * 50 + (k - 8)];
    if (k >= 58 && k < 108) return Whh1[g * 50 + (k - 58)];
    return 0.f;
}

__global__ void __launch_bounds__(NTHR, 1)
lstm_mma2_kernel(const float* __restrict__ x,
                 const float* __restrict__ Wih0, const float* __restrict__ Whh0,
                 const float* __restrict__ bih0, const float* __restrict__ bhh0,
                 const float* __restrict__ Wih1, const float* __restrict__ Whh1,
                 const float* __restrict__ bih1, const float* __restrict__ bhh1,
                 const float* __restrict__ Wlin, const float* __restrict__ blin,
                 float* __restrict__ out)
{
    extern __shared__ char sm[];
    const u32 smb = smem_u32(sm);
    const int tid  = threadIdx.x;
    const int cta  = blockIdx.x;
    const int lane = tid & 31;
    const int wrp  = tid >> 5;
    const int m0   = wrp * 16;

    float* bias0 = (float*)(sm + SM_BIAS0);
    float* bias1 = (float*)(sm + SM_BIAS1);
    float* wl    = (float*)(sm + SM_WL);

    // ---- init staging ----
    for (int i = tid; i < 200; i += NTHR){
        bias0[i] = bih0[i] + bhh0[i];
        bias1[i] = bih1[i] + bhh1[i];
    }
    if (tid < HN) wl[tid] = Wlin[tid];
    if (tid == HN) wl[HN] = blin[0];
    for (int i = tid; i < 4 * BT8 / 4; i += NTHR)
        ((u32*)(sm + SM_B))[i] = 0;
    for (int i = tid; i < 208 * 112; i += NTHR){
        const int g = i / 112, k = i % 112;
        const float v = a1elem(g, k, Wih1, Whh1);
        const float lo = v - __bfloat162float(__float2bfloat16_rn(v));
        *(__nv_bfloat16*)(sm + SM_A1LO + g * BROW + k * 2) = __float2bfloat16_rn(lo);
    }

    // ---- register A fragments ----
    const int gid = lane >> 2;
    const int c0  = (lane & 3) * 2;
    u32 A0hi[4][4], A0lo[4][4], A1hi[7][4];
#pragma unroll
    for (int kt = 0; kt < 4; ++kt)
#pragma unroll
        for (int q = 0; q < 4; ++q){
            const int g = m0 + gid + ((q & 1) ? 8 : 0);
            const int k = kt * 16 + c0 + ((q & 2) ? 8 : 0);
            const float e0 = a0elem(g, k,     Whh0, Wih0);
            const float e1 = a0elem(g, k + 1, Whh0, Wih0);
            const __nv_bfloat16 h0b = __float2bfloat16_rn(e0);
            const __nv_bfloat16 h1b = __float2bfloat16_rn(e1);
            A0hi[kt][q] = pk2bf(h0b, h1b);
            A0lo[kt][q] = pk2bf(__float2bfloat16_rn(e0 - __bfloat162float(h0b)),
                                __float2bfloat16_rn(e1 - __bfloat162float(h1b)));
        }
#pragma unroll
    for (int kt = 0; kt < 7; ++kt)
#pragma unroll
        for (int q = 0; q < 4; ++q){
            const int g = m0 + gid + ((q & 1) ? 8 : 0);
            const int k = kt * 16 + c0 + ((q & 2) ? 8 : 0);
            A1hi[kt][q] = pk2bf(__float2bfloat16_rn(a1elem(g, k,     Wih1, Whh1)),
                                __float2bfloat16_rn(a1elem(g, k + 1, Wih1, Whh1)));
        }

    // ---- ldsm lane offsets ----
    const int ln8 = lane & 7, grp = lane >> 3;
    const u32 a1loLane = smb + SM_A1LO
                       + (u32)((m0 + ln8 + ((grp & 1) ? 8 : 0)) * BROW + ((grp >= 2) ? 16 : 0));
    const u32 bOffLane = (u32)((lane & 7) * BROW + (((lane >> 3) & 1) ? 16 : 0));

    // ---- act roles (tid < 400): same (lay, aj, ae2) for both groups ----
    const bool is_act = (tid < 400);
    const int layA = (tid < 200) ? 0 : 1;
    const int at   = (tid < 200) ? tid : tid - 200;
    const int aj   = at % 50;
    const int ae2  = (at / 50) * 2;

    // ---- stager roles (tid 400..415) ----
    const int st   = tid - 400;
    const int sgrp = st >> 3;          // 0 = group A, 1 = group B
    const int se   = st & 7;
    const float* xgp = (tid >= 400) ? (x + ((size_t)(cta * EN + sgrp * 8 + se) * TN) * 8) : x;

    __syncthreads();   // zeroing complete before x(0) staging

    float xv[8];
    if (tid >= 400){
        if (sgrp == 0){
            // stage x_A(0) now, prefetch x_A(1)
#pragma unroll
            for (int d = 0; d < 8; ++d) xv[d] = xgp[d];
            char* bh = sm + SM_B;          // group A hi
            u32 hw[4], lw[4];
#pragma unroll
            for (int i = 0; i < 4; ++i){
                const float a = xv[2*i], b = xv[2*i+1];
                const __nv_bfloat16 ha = __float2bfloat16_rn(a), hb = __float2bfloat16_rn(b);
                hw[i] = pk2bf(ha, hb);
                lw[i] = pk2bf(__float2bfloat16_rn(a - __bfloat162float(ha)),
                              __float2bfloat16_rn(b - __bfloat162float(hb)));
            }
            *(uint4*)(bh + se * BROW)        = *(uint4*)hw;
            *(uint4*)(bh + BT8 + se * BROW)  = *(uint4*)lw;
#pragma unroll
            for (int d = 0; d < 8; ++d) xv[d] = xgp[8 + d];
        } else {
            // hold x_B(0); staged at segment 0
#pragma unroll
            for (int d = 0; d < 8; ++d) xv[d] = xgp[d];
        }
    }

    float bi = 0.f, bf_ = 0.f, bg = 0.f, bo = 0.f;
    if (is_act){
        const float* bp = layA ? bias1 : bias0;
        bi = bp[aj]; bf_ = bp[aj + 50]; bg = bp[aj + 100]; bo = bp[aj + 150];
    }
    float cc[4] = {0.f, 0.f, 0.f, 0.f};   // cc[group*2 + m]

    // ============ segment loop ============
    // even s=2p: MMA_A(p) + act_B(p-1) + stage x_B(p)
    // odd  s=2p+1: MMA_B(p) + act_A(p) + stage x_A(p+1)
    for (int s = 0; s <= 2 * TN + 2; ++s){
        __syncthreads();

        const int mg = s & 1;          // MMA group
        const int p  = s >> 1;         // MMA phase
        const int ag = mg ^ 1;         // act group
        const int q  = (s - 1) >> 1;   // act step (s=0 -> -1)

        // ---------------- MMA ----------------
        if (p <= TN){
            float acc0a[4] = {0,0,0,0}, acc0b[4] = {0,0,0,0};
            float acc1a[4] = {0,0,0,0}, acc1b[4] = {0,0,0,0};
            const u32 bhA = smb + SM_B + (u32)(mg * 2 * BT8) + bOffLane;
            const u32 blA = bhA + BT8;
#pragma unroll
            for (int kt = 0; kt < 7; ++kt){
                u32 bh[2], bl[2], wlo[4];
                ldsm2(bh, bhA + kt * 32);
                ldsm2(bl, blA + kt * 32);
                ldsm4(wlo, a1loLane + kt * 32);
                float* a1 = (kt & 1) ? acc1b : acc1a;
                mma_bf16(a1, A1hi[kt], bh[0], bh[1]);
                mma_bf16(a1, wlo,      bh[0], bh[1]);
                mma_bf16(a1, A1hi[kt], bl[0], bl[1]);
                if (kt < 4){
                    float* a0 = (kt & 1) ? acc0b : acc0a;
                    mma_bf16(a0, A0hi[kt], bh[0], bh[1]);
                    mma_bf16(a0, A0lo[kt], bh[0], bh[1]);
                    mma_bf16(a0, A0hi[kt], bl[0], bl[1]);
                }
            }
            float* G0 = (float*)(sm + SM_G) + (mg * 2 + 0) * 2080;
            float* G1 = (float*)(sm + SM_G) + (mg * 2 + 1) * 2080;
            const int r = m0 + gid;
            *(float2*)(G0 + r * 10 + c0)       = make_float2(acc0a[0] + acc0b[0], acc0a[1] + acc0b[1]);
            *(float2*)(G0 + (r + 8) * 10 + c0) = make_float2(acc0a[2] + acc0b[2], acc0a[3] + acc0b[3]);
            *(float2*)(G1 + r * 10 + c0)       = make_float2(acc1a[0] + acc1b[0], acc1a[1] + acc1b[1]);
            *(float2*)(G1 + (r + 8) * 10 + c0) = make_float2(acc1a[2] + acc1b[2], acc1a[3] + acc1b[3]);
        }

        // ---------------- activations (other group) ----------------
        if (is_act && q >= 0){
            const bool do0 = (layA == 0) && (q < TN);
            const bool do1 = (layA == 1) && (q >= 1);
            if (do0 || do1){
                const float* G = (float*)(sm + SM_G) + (ag * 2 + layA) * 2080;
                const float2 gi = *(const float2*)(G + aj * 10 + ae2);
                const float2 gf = *(const float2*)(G + (aj + 50) * 10 + ae2);
                const float2 gg = *(const float2*)(G + (aj + 100) * 10 + ae2);
                const float2 go = *(const float2*)(G + (aj + 150) * 10 + ae2);
                float v0, v1;
                {
                    const float i0 = sigf(gi.x + bi), f0 = sigf(gf.x + bf_);
                    const float q0 = tanhx(gg.x + bg), o0 = sigf(go.x + bo);
                    float& c0r = cc[ag * 2 + 0];
                    c0r = fmaf(f0, c0r, i0 * q0); v0 = o0 * tanhx(c0r);
                    const float i1 = sigf(gi.y + bi), f1 = sigf(gf.y + bf_);
                    const float q1 = tanhx(gg.y + bg), o1 = sigf(go.y + bo);
                    float& c1r = cc[ag * 2 + 1];
                    c1r = fmaf(f1, c1r, i1 * q1); v1 = o1 * tanhx(c1r);
                }
                if (layA == 1 && q == TN){
                    // final h1(TN-1): stash f32 for head into G0 of this group
                    float* GS = (float*)(sm + SM_G) + (ag * 2 + 0) * 2080;
                    *(float2*)(GS + aj * 10 + ae2) = make_float2(v0, v1);
                } else {
                    char* bh = sm + SM_B + ag * 2 * BT8;
                    char* bl = bh + BT8;
                    const int col = layA ? (58 + aj) : (8 + aj);
                    const __nv_bfloat16 h0v = __float2bfloat16_rn(v0);
                    const __nv_bfloat16 h1v = __float2bfloat16_rn(v1);
                    *(__nv_bfloat16*)(bh + (ae2 + 0) * BROW + col * 2) = h0v;
                    *(__nv_bfloat16*)(bh + (ae2 + 1) * BROW + col * 2) = h1v;
                    *(__nv_bfloat16*)(bl + (ae2 + 0) * BROW + col * 2) =
                        __float2bfloat16_rn(v0 - __bfloat162float(h0v));
                    *(__nv_bfloat16*)(bl + (ae2 + 1) * BROW + col * 2) =
                        __float2bfloat16_rn(v1 - __bfloat162float(h1v));
                }
            }
        }

        // ---------------- x staging ----------------
        if (tid >= 400){
            const bool active = (sgrp == 0) ? ((s & 1) == 1) : ((s & 1) == 0);
            if (active){
                const int tx = (sgrp == 0) ? (p + 1) : p;
                if (tx < TN){
                    char* bh = sm + SM_B + sgrp * 2 * BT8;
                    u32 hw[4], lw[4];
#pragma unroll
                    for (int i = 0; i < 4; ++i){
                        const float a = xv[2*i], b = xv[2*i+1];
                        const __nv_bfloat16 ha = __float2bfloat16_rn(a), hb = __float2bfloat16_rn(b);
                        hw[i] = pk2bf(ha, hb);
                        lw[i] = pk2bf(__float2bfloat16_rn(a - __bfloat162float(ha)),
                                      __float2bfloat16_rn(b - __bfloat162float(hb)));
                    }
                    *(uint4*)(bh + se * BROW)       = *(uint4*)hw;
                    *(uint4*)(bh + BT8 + se * BROW) = *(uint4*)lw;
                    int tn = tx + 1; if (tn > TN - 1) tn = TN - 1;
#pragma unroll
                    for (int d = 0; d < 8; ++d) xv[d] = xgp[(size_t)tn * 8 + d];
                }
            }
        }
    }

    __syncthreads();

    // ---- linear head: stashed h1 f32 at G0 of each group ----
    if (tid < EN){
        const int g = tid >> 3, e = tid & 7;
        const float* GS = (float*)(sm + SM_G) + (g * 2 + 0) * 2080;
        float acc = wl[HN];
#pragma unroll 10
        for (int j = 0; j < HN; ++j)
            acc = fmaf(GS[j * 10 + e], wl[j], acc);
        out[cta * EN + tid] = acc;
    }
}

extern "C" void kernel_launch(void* const* d_in, const int* in_sizes, int n_in,
                              void* d_out, int out_size)
{
    const float* x    = (const float*)d_in[0];
    const float* Wih0 = (const float*)d_in[1];
    const float* Whh0 = (const float*)d_in[2];
    const float* bih0 = (const float*)d_in[3];
    const float* bhh0 = (const float*)d_in[4];
    const float* Wih1 = (const float*)d_in[5];
    const float* Whh1 = (const float*)d_in[6];
    const float* bih1 = (const float*)d_in[7];
    const float* bhh1 = (const float*)d_in[8];
    const float* Wlin = (const float*)d_in[9];
    const float* blin = (const float*)d_in[10];
    float* out = (float*)d_out;

    cudaFuncSetAttribute(lstm_mma2_kernel,
                         cudaFuncAttributeMaxDynamicSharedMemorySize, SMEM_BYTES);
    lstm_mma2_kernel<<<NCTA, NTHR, SMEM_BYTES>>>(
        x, Wih0, Whh0, bih0, bhh0, Wih1, Whh1, bih1, bhh1, Wlin, blin, out);
}

// round 9
// speedup vs baseline: 1.3369x; 1.3369x over previous
#include <cuda_runtime.h>
#include <cuda_bf16.h>
#include <cstdint>

typedef uint32_t u32;

#define HN 50
#define TN 512
#define EN 16
#define NCTA 128
#define NTHR 416   // 13 warps

#define BROW 272
#define BT   (16*BROW)        // 4352 one tile (16 rows x 272B)
// K layout in B tiles: cols 0-7 = x, 8-57 = h0, 58-107 = h1, 108-135 pad
#define SM_B     0            // [2 buf][hi,lo] = 4*4352 = 17408
#define SM_A1LO  17408        // [208][272] = 56576  (unit-interleaved rows)
#define SM_G     73984        // 13 warps * 2 lay * 16*18 f32 = 29952
#define SM_BIAS  103936       // [2][200] f32 = 1600
#define SM_WL    105536       // 51 f32 -> 256
#define SM_HEAD  105792       // [50][16] f32 = 3200
#define SMEM_BYTES 108992

__device__ __forceinline__ u32 smem_u32(const void* p){
    u32 a; asm("{ .reg .u64 t; cvta.to.shared.u64 t, %1; cvt.u32.u64 %0, t; }" : "=r"(a) : "l"(p));
    return a;
}
__device__ __forceinline__ u32 pk2bf(__nv_bfloat16 a, __nv_bfloat16 b){
    return (u32)__bfloat16_as_ushort(a) | ((u32)__bfloat16_as_ushort(b) << 16);
}
__device__ __forceinline__ void mma_bf16(float* c, const u32* a, u32 b0, u32 b1){
    asm volatile("mma.sync.aligned.m16n8k16.row.col.f32.bf16.bf16.f32 "
                 "{%0,%1,%2,%3}, {%4,%5,%6,%7}, {%8,%9}, {%0,%1,%2,%3};"
                 : "+f"(c[0]), "+f"(c[1]), "+f"(c[2]), "+f"(c[3])
                 : "r"(a[0]), "r"(a[1]), "r"(a[2]), "r"(a[3]), "r"(b0), "r"(b1));
}
__device__ __forceinline__ void ldsm4(u32* r, u32 addr){
    asm volatile("ldmatrix.sync.aligned.m8n8.x4.shared.b16 {%0,%1,%2,%3}, [%4];"
                 : "=r"(r[0]), "=r"(r[1]), "=r"(r[2]), "=r"(r[3]) : "r"(addr));
}
__device__ __forceinline__ float sigf(float v){
    return __fdividef(1.f, 1.f + __expf(-v));
}
__device__ __forceinline__ float tanhx(float v){
    return fmaf(2.f, __fdividef(1.f, 1.f + __expf(-2.f * v)), -1.f);
}

// interleaved A-row mapping: global row rr -> warp w=rr>>4, local r=rr&15,
// unit u = 4w + (r>>2), gate t = r&3, original gate row grow = t*50+u
__device__ __forceinline__ float a0elem_i(int w, int r, int k,
                                          const float* Whh0, const float* Wih0){
    const int u = 4*w + (r >> 2), t = r & 3;
    if (u >= HN) return 0.f;
    const int g = t * 50 + u;
    if (k < 8)  return Wih0[g * 8 + k];
    if (k < 58) return Whh0[g * 50 + (k - 8)];
    return 0.f;
}
__device__ __forceinline__ float a1elem_i(int w, int r, int k,
                                          const float* Wih1, const float* Whh1){
    const int u = 4*w + (r >> 2), t = r & 3;
    if (u >= HN) return 0.f;
    const int g = t * 50 + u;
    if (k >= 8  && k < 58)  return Wih1[g * 50 + (k - 8)];
    if (k >= 58 && k < 108) return Whh1[g * 50 + (k - 58)];
    return 0.f;
}

__global__ void __launch_bounds__(NTHR, 1)
lstm_mma3_kernel(const float* __restrict__ x,
                 const float* __restrict__ Wih0, const float* __restrict__ Whh0,
                 const float* __restrict__ bih0, const float* __restrict__ bhh0,
                 const float* __restrict__ Wih1, const float* __restrict__ Whh1,
                 const float* __restrict__ bih1, const float* __restrict__ bhh1,
                 const float* __restrict__ Wlin, const float* __restrict__ blin,
                 float* __restrict__ out)
{
    extern __shared__ char sm[];
    const u32 smb = smem_u32(sm);
    const int tid  = threadIdx.x;
    const int cta  = blockIdx.x;
    const int lane = tid & 31;
    const int wrp  = tid >> 5;
    const int m0   = wrp * 16;

    float* bias = (float*)(sm + SM_BIAS);   // [2][200]
    float* wl   = (float*)(sm + SM_WL);

    // ---- init staging ----
    for (int i = tid; i < 200; i += NTHR){
        bias[i]       = bih0[i] + bhh0[i];
        bias[200 + i] = bih1[i] + bhh1[i];
    }
    if (tid < HN) wl[tid] = Wlin[tid];
    if (tid == HN) wl[HN] = blin[0];
    for (int i = tid; i < 4 * BT / 4; i += NTHR)
        ((u32*)(sm + SM_B))[i] = 0;
    // A1 lo tile (interleaved rows)
    for (int i = tid; i < 208 * 136; i += NTHR){
        const int rr = i / 136, k = i % 136;
        float lo = 0.f;
        if (k < 112){
            const float v = a1elem_i(rr >> 4, rr & 15, k, Wih1, Whh1);
            lo = v - __bfloat162float(__float2bfloat16_rn(v));
        }
        *(__nv_bfloat16*)(sm + SM_A1LO + rr * BROW + k * 2) = __float2bfloat16_rn(lo);
    }

    // ---- register A fragments (interleaved rows) ----
    const int gid = lane >> 2;
    const int c0  = (lane & 3) * 2;
    u32 A0hi[4][4], A0lo[4][4], A1hi[7][4];
#pragma unroll
    for (int kt = 0; kt < 4; ++kt)
#pragma unroll
        for (int q = 0; q < 4; ++q){
            const int r = gid + ((q & 1) ? 8 : 0);
            const int k = kt * 16 + c0 + ((q & 2) ? 8 : 0);
            const float e0 = a0elem_i(wrp, r, k,     Whh0, Wih0);
            const float e1 = a0elem_i(wrp, r, k + 1, Whh0, Wih0);
            const __nv_bfloat16 h0b = __float2bfloat16_rn(e0);
            const __nv_bfloat16 h1b = __float2bfloat16_rn(e1);
            A0hi[kt][q] = pk2bf(h0b, h1b);
            A0lo[kt][q] = pk2bf(__float2bfloat16_rn(e0 - __bfloat162float(h0b)),
                                __float2bfloat16_rn(e1 - __bfloat162float(h1b)));
        }
#pragma unroll
    for (int kt = 0; kt < 7; ++kt)
#pragma unroll
        for (int q = 0; q < 4; ++q){
            const int r = gid + ((q & 1) ? 8 : 0);
            const int k = kt * 16 + c0 + ((q & 2) ? 8 : 0);
            A1hi[kt][q] = pk2bf(__float2bfloat16_rn(a1elem_i(wrp, r, k,     Wih1, Whh1)),
                                __float2bfloat16_rn(a1elem_i(wrp, r, k + 1, Wih1, Whh1)));
        }

    // ---- ldsm lane offsets (same scheme as validated R7) ----
    const int ln8 = lane & 7, grp = lane >> 3;
    const u32 bOffLane = (u32)((ln8 + ((grp >= 2) ? 8 : 0)) * BROW + ((grp & 1) ? 16 : 0));
    const u32 a1loLane = smb + SM_A1LO
                       + (u32)((m0 + ln8 + ((grp & 1) ? 8 : 0)) * BROW + ((grp >= 2) ? 16 : 0));

    // ---- act roles: lane handles units {4w+ua, 4w+ua+2}, elem e ----
    const int e  = lane & 15;
    const int ua = lane >> 4;      // 0 or 1
    float* gw = (float*)(sm + SM_G) + wrp * 576;   // [2 lay][16 rows][18]

    // ---- x staging roles: tid<128 -> (xe, xd) ----
    const int xd = tid & 7, xe = tid >> 3;
    const float* xgp = (tid < 128) ? (x + ((size_t)(cta * EN + xe) * TN) * 8 + xd) : x;

    __syncthreads();   // staging visible

    // bias regs: bsr[lay*8 + t*2 + ui]
    float bsr[16];
#pragma unroll
    for (int lay = 0; lay < 2; ++lay)
#pragma unroll
        for (int t = 0; t < 4; ++t)
#pragma unroll
            for (int ui = 0; ui < 2; ++ui){
                const int u = 4 * wrp + ua + 2 * ui;
                bsr[lay * 8 + t * 2 + ui] = (u < HN) ? bias[lay * 200 + t * 50 + u] : 0.f;
            }

    // stage x(0) into buf0, prefetch x(1)
    float xv = 0.f;
    if (tid < 128){
        const float v = xgp[0];
        const __nv_bfloat16 hv = __float2bfloat16_rn(v);
        *(__nv_bfloat16*)(sm + SM_B + xe * BROW + xd * 2) = hv;
        *(__nv_bfloat16*)(sm + SM_B + BT + xe * BROW + xd * 2) =
            __float2bfloat16_rn(v - __bfloat162float(hv));
        xv = xgp[8];
    }

    float cc[4] = {0.f, 0.f, 0.f, 0.f};   // [lay*2 + ui]

    // ================= phase loop (ONE barrier per phase) =================
    for (int p = 0; p <= TN; ++p){
        const int b = p & 1, nb = b ^ 1;

        __syncthreads();   // B[b] (h, x) ready; B[nb] free for writes

        // ---------------- MMA ----------------
        float acc0[2][4] = {{0,0,0,0},{0,0,0,0}};
        float acc1[2][4] = {{0,0,0,0},{0,0,0,0}};
        {
            const u32 bhA = smb + SM_B + (u32)(b * 2 * BT) + bOffLane;
            const u32 blA = bhA + BT;
#pragma unroll
            for (int kt = 0; kt < 7; ++kt){
                u32 bh[4], bl[4], wlo[4];
                ldsm4(bh, bhA + kt * 32);
                ldsm4(bl, blA + kt * 32);
                ldsm4(wlo, a1loLane + kt * 32);
                mma_bf16(acc1[0], A1hi[kt], bh[0], bh[1]); mma_bf16(acc1[1], A1hi[kt], bh[2], bh[3]);
                mma_bf16(acc1[0], wlo,      bh[0], bh[1]); mma_bf16(acc1[1], wlo,      bh[2], bh[3]);
                mma_bf16(acc1[0], A1hi[kt], bl[0], bl[1]); mma_bf16(acc1[1], A1hi[kt], bl[2], bl[3]);
                if (kt < 4){
                    mma_bf16(acc0[0], A0hi[kt], bh[0], bh[1]); mma_bf16(acc0[1], A0hi[kt], bh[2], bh[3]);
                    mma_bf16(acc0[0], A0lo[kt], bh[0], bh[1]); mma_bf16(acc0[1], A0lo[kt], bh[2], bh[3]);
                    mma_bf16(acc0[0], A0hi[kt], bl[0], bl[1]); mma_bf16(acc0[1], A0hi[kt], bl[2], bl[3]);
                }
            }
        }

        // ---------------- gates -> warp-private scratch ----------------
        {
            const int r0 = gid, r1 = gid + 8;
            *(float2*)(gw + r0 * 18 + c0)       = make_float2(acc0[0][0], acc0[0][1]);
            *(float2*)(gw + r1 * 18 + c0)       = make_float2(acc0[0][2], acc0[0][3]);
            *(float2*)(gw + r0 * 18 + 8 + c0)   = make_float2(acc0[1][0], acc0[1][1]);
            *(float2*)(gw + r1 * 18 + 8 + c0)   = make_float2(acc0[1][2], acc0[1][3]);
            float* g1 = gw + 288;
            *(float2*)(g1 + r0 * 18 + c0)       = make_float2(acc1[0][0], acc1[0][1]);
            *(float2*)(g1 + r1 * 18 + c0)       = make_float2(acc1[0][2], acc1[0][3]);
            *(float2*)(g1 + r0 * 18 + 8 + c0)   = make_float2(acc1[1][0], acc1[1][1]);
            *(float2*)(g1 + r1 * 18 + 8 + c0)   = make_float2(acc1[1][2], acc1[1][3]);
        }
        __syncwarp(0xffffffffu);

        // ---------------- activations (warp-local) ----------------
        char* bwh = sm + SM_B + nb * 2 * BT;   // next-buffer hi tile
        char* bwl = bwh + BT;
#pragma unroll
        for (int lay = 0; lay < 2; ++lay){
            if (lay == 0 ? (p >= TN) : (p < 1)) continue;
            const float* g = gw + lay * 288;
#pragma unroll
            for (int ui = 0; ui < 2; ++ui){
                const int up = ua + 2 * ui;
                const int u  = 4 * wrp + up;
                if (u >= HN) continue;
                const float gi = g[(4 * up + 0) * 18 + e] + bsr[lay * 8 + 0 + ui];
                const float gf = g[(4 * up + 1) * 18 + e] + bsr[lay * 8 + 2 + ui];
                const float gg = g[(4 * up + 2) * 18 + e] + bsr[lay * 8 + 4 + ui];
                const float go = g[(4 * up + 3) * 18 + e] + bsr[lay * 8 + 6 + ui];
                const float i_ = sigf(gi), f_ = sigf(gf);
                const float q_ = tanhx(gg), o_ = sigf(go);
                float& c = cc[lay * 2 + ui];
                c = fmaf(f_, c, i_ * q_);
                const float v = o_ * tanhx(c);
                if (lay == 1 && p == TN){
                    ((float*)(sm + SM_HEAD))[u * 16 + e] = v;   // final h1 stash
                } else {
                    const int col = lay ? (58 + u) : (8 + u);
                    const __nv_bfloat16 hv = __float2bfloat16_rn(v);
                    *(__nv_bfloat16*)(bwh + e * BROW + col * 2) = hv;
                    *(__nv_bfloat16*)(bwl + e * BROW + col * 2) =
                        __float2bfloat16_rn(v - __bfloat162float(hv));
                }
            }
        }

        // ---------------- x staging: x(p+1) -> buf nb ----------------
        if (tid < 128 && (p + 1) < TN){
            const __nv_bfloat16 hv = __float2bfloat16_rn(xv);
            *(__nv_bfloat16*)(bwh + xe * BROW + xd * 2) = hv;
            *(__nv_bfloat16*)(bwl + xe * BROW + xd * 2) =
                __float2bfloat16_rn(xv - __bfloat162float(hv));
            int tn = p + 2; if (tn > TN - 1) tn = TN - 1;
            xv = xgp[(size_t)tn * 8];
        }
    }

    __syncthreads();

    // ---- linear head on stashed final h1 ----
    if (tid < EN){
        const float* hd = (const float*)(sm + SM_HEAD);
        float acc = wl[HN];
#pragma unroll 10
        for (int j = 0; j < HN; ++j)
            acc = fmaf(hd[j * 16 + tid], wl[j], acc);
        out[cta * EN + tid] = acc;
    }
}

extern "C" void kernel_launch(void* const* d_in, const int* in_sizes, int n_in,
                              void* d_out, int out_size)
{
    const float* x    = (const float*)d_in[0];
    const float* Wih0 = (const float*)d_in[1];
    const float* Whh0 = (const float*)d_in[2];
    const float* bih0 = (const float*)d_in[3];
    const float* bhh0 = (const float*)d_in[4];
    const float* Wih1 = (const float*)d_in[5];
    const float* Whh1 = (const float*)d_in[6];
    const float* bih1 = (const float*)d_in[7];
    const float* bhh1 = (const float*)d_in[8];
    const float* Wlin = (const float*)d_in[9];
    const float* blin = (const float*)d_in[10];
    float* out = (float*)d_out;

    cudaFuncSetAttribute(lstm_mma3_kernel,
                         cudaFuncAttributeMaxDynamicSharedMemorySize, SMEM_BYTES);
    lstm_mma3_kernel<<<NCTA, NTHR, SMEM_BYTES>>>(
        x, Wih0, Whh0, bih0, bhh0, Wih1, Whh1, bih1, bhh1, Wlin, blin, out);
}

// round 10
// speedup vs baseline: 1.7232x; 1.2890x over previous
#include <cuda_runtime.h>
#include <cuda_fp16.h>
#include <cstdint>

typedef uint32_t u32;

#define HN 50
#define TN 512
#define EN 16
#define NCTA 128
#define NTHR 416   // 13 warps

#define BROW 272
#define BT   (16*BROW)        // 4352 one tile (16 rows x 272B), fp16 elems
// K layout in B tiles: cols 0-7 = x, 8-57 = h0, 58-107 = h1, 108-135 pad
#define SM_B     0            // [2 buf][hi,lo] = 4*4352 = 17408
#define SM_G     17408        // 13 warps * 2 lay * 16*18 f32 = 29952
#define SM_BIAS  47360        // [2][200] f32 = 1600
#define SM_WL    48960        // 51 f32 -> 256
#define SM_HEAD  49216        // [50][16] f32 = 3200
#define SMEM_BYTES 52416

__device__ __forceinline__ u32 smem_u32(const void* p){
    u32 a; asm("{ .reg .u64 t; cvta.to.shared.u64 t, %1; cvt.u32.u64 %0, t; }" : "=r"(a) : "l"(p));
    return a;
}
__device__ __forceinline__ u32 pk2h(__half a, __half b){
    return (u32)__half_as_ushort(a) | ((u32)__half_as_ushort(b) << 16);
}
__device__ __forceinline__ void mma_f16(float* c, const u32* a, u32 b0, u32 b1){
    asm volatile("mma.sync.aligned.m16n8k16.row.col.f32.f16.f16.f32 "
                 "{%0,%1,%2,%3}, {%4,%5,%6,%7}, {%8,%9}, {%0,%1,%2,%3};"
                 : "+f"(c[0]), "+f"(c[1]), "+f"(c[2]), "+f"(c[3])
                 : "r"(a[0]), "r"(a[1]), "r"(a[2]), "r"(a[3]), "r"(b0), "r"(b1));
}
__device__ __forceinline__ void ldsm4(u32* r, u32 addr){
    asm volatile("ldmatrix.sync.aligned.m8n8.x4.shared.b16 {%0,%1,%2,%3}, [%4];"
                 : "=r"(r[0]), "=r"(r[1]), "=r"(r[2]), "=r"(r[3]) : "r"(addr));
}
__device__ __forceinline__ float sigf(float v){
    return __fdividef(1.f, 1.f + __expf(-v));
}
__device__ __forceinline__ float tanhx(float v){
    return fmaf(2.f, __fdividef(1.f, 1.f + __expf(-2.f * v)), -1.f);
}

// interleaved A-row mapping: warp w, local r: unit u = 4w + (r>>2), gate t = r&3
__device__ __forceinline__ float a0elem_i(int w, int r, int k,
                                          const float* Whh0, const float* Wih0){
    const int u = 4*w + (r >> 2), t = r & 3;
    if (u >= HN) return 0.f;
    const int g = t * 50 + u;
    if (k < 8)  return Wih0[g * 8 + k];
    if (k < 58) return Whh0[g * 50 + (k - 8)];
    return 0.f;
}
__device__ __forceinline__ float a1elem_i(int w, int r, int k,
                                          const float* Wih1, const float* Whh1){
    const int u = 4*w + (r >> 2), t = r & 3;
    if (u >= HN) return 0.f;
    const int g = t * 50 + u;
    if (k >= 8  && k < 58)  return Wih1[g * 50 + (k - 8)];
    if (k >= 58 && k < 108) return Whh1[g * 50 + (k - 58)];
    return 0.f;
}

__global__ void __launch_bounds__(NTHR, 1)
lstm_mma4_kernel(const float* __restrict__ x,
                 const float* __restrict__ Wih0, const float* __restrict__ Whh0,
                 const float* __restrict__ bih0, const float* __restrict__ bhh0,
                 const float* __restrict__ Wih1, const float* __restrict__ Whh1,
                 const float* __restrict__ bih1, const float* __restrict__ bhh1,
                 const float* __restrict__ Wlin, const float* __restrict__ blin,
                 float* __restrict__ out)
{
    extern __shared__ char sm[];
    const u32 smb = smem_u32(sm);
    const int tid  = threadIdx.x;
    const int cta  = blockIdx.x;
    const int lane = tid & 31;
    const int wrp  = tid >> 5;

    float* bias = (float*)(sm + SM_BIAS);   // [2][200]
    float* wl   = (float*)(sm + SM_WL);

    // ---- init staging ----
    for (int i = tid; i < 200; i += NTHR){
        bias[i]       = bih0[i] + bhh0[i];
        bias[200 + i] = bih1[i] + bhh1[i];
    }
    if (tid < HN) wl[tid] = Wlin[tid];
    if (tid == HN) wl[HN] = blin[0];
    for (int i = tid; i < 4 * BT / 4; i += NTHR)
        ((u32*)(sm + SM_B))[i] = 0;

    // ---- register A fragments (fp16, unsplit W; interleaved rows) ----
    const int gid = lane >> 2;
    const int c0  = (lane & 3) * 2;
    u32 A0[4][4], A1[7][4];
#pragma unroll
    for (int kt = 0; kt < 4; ++kt)
#pragma unroll
        for (int q = 0; q < 4; ++q){
            const int r = gid + ((q & 1) ? 8 : 0);
            const int k = kt * 16 + c0 + ((q & 2) ? 8 : 0);
            A0[kt][q] = pk2h(__float2half_rn(a0elem_i(wrp, r, k,     Whh0, Wih0)),
                             __float2half_rn(a0elem_i(wrp, r, k + 1, Whh0, Wih0)));
        }
#pragma unroll
    for (int kt = 0; kt < 7; ++kt)
#pragma unroll
        for (int q = 0; q < 4; ++q){
            const int r = gid + ((q & 1) ? 8 : 0);
            const int k = kt * 16 + c0 + ((q & 2) ? 8 : 0);
            A1[kt][q] = pk2h(__float2half_rn(a1elem_i(wrp, r, k,     Wih1, Whh1)),
                             __float2half_rn(a1elem_i(wrp, r, k + 1, Wih1, Whh1)));
        }

    // ---- ldsm lane offsets (validated R7/R9 scheme) ----
    const int ln8 = lane & 7, grp = lane >> 3;
    const u32 bOffLane = (u32)((ln8 + ((grp >= 2) ? 8 : 0)) * BROW + ((grp & 1) ? 16 : 0));

    // ---- act roles: lane handles units {4w+ua, 4w+ua+2}, elem e ----
    const int e  = lane & 15;
    const int ua = lane >> 4;      // 0 or 1
    float* gw = (float*)(sm + SM_G) + wrp * 576;   // [2 lay][16 rows][18]

    // ---- x staging roles: tid<128 -> (xe, xd) ----
    const int xd = tid & 7, xe = tid >> 3;
    const float* xgp = (tid < 128) ? (x + ((size_t)(cta * EN + xe) * TN) * 8 + xd) : x;

    __syncthreads();   // staging visible

    // bias regs: bsr[lay*8 + t*2 + ui]
    float bsr[16];
#pragma unroll
    for (int lay = 0; lay < 2; ++lay)
#pragma unroll
        for (int t = 0; t < 4; ++t)
#pragma unroll
            for (int ui = 0; ui < 2; ++ui){
                const int u = 4 * wrp + ua + 2 * ui;
                bsr[lay * 8 + t * 2 + ui] = (u < HN) ? bias[lay * 200 + t * 50 + u] : 0.f;
            }

    // stage x(0) into buf0, prefetch x(1)
    float xv = 0.f;
    if (tid < 128){
        const float v = xgp[0];
        const __half hv = __float2half_rn(v);
        *(__half*)(sm + SM_B + xe * BROW + xd * 2) = hv;
        *(__half*)(sm + SM_B + BT + xe * BROW + xd * 2) =
            __float2half_rn(v - __half2float(hv));
        xv = xgp[8];
    }

    float cc[4] = {0.f, 0.f, 0.f, 0.f};   // [lay*2 + ui]

    // ================= phase loop (one barrier per phase) =================
    for (int p = 0; p <= TN; ++p){
        const int b = p & 1, nb = b ^ 1;

        __syncthreads();   // B[b] ready; B[nb] free

        // ---------------- MMA: 2 passes (B-hi, B-lo), fp16 ----------------
        float acc0a[4] = {0,0,0,0}, acc0b[4] = {0,0,0,0};
        float acc0c[4] = {0,0,0,0}, acc0d[4] = {0,0,0,0};
        float acc1a[4] = {0,0,0,0}, acc1b[4] = {0,0,0,0};
        float acc1c[4] = {0,0,0,0}, acc1d[4] = {0,0,0,0};
        {
            const u32 bhA = smb + SM_B + (u32)(b * 2 * BT) + bOffLane;
            const u32 blA = bhA + BT;
#pragma unroll
            for (int kt = 0; kt < 7; ++kt){
                u32 bh[4], bl[4];
                ldsm4(bh, bhA + kt * 32);
                ldsm4(bl, blA + kt * 32);
                float* p1a = (kt & 1) ? acc1b : acc1a;   // split chains by kt parity
                float* p1c = (kt & 1) ? acc1d : acc1c;
                mma_f16(p1a, A1[kt], bh[0], bh[1]); mma_f16(p1c, A1[kt], bh[2], bh[3]);
                mma_f16(p1a, A1[kt], bl[0], bl[1]); mma_f16(p1c, A1[kt], bl[2], bl[3]);
                if (kt < 4){
                    float* p0a = (kt & 1) ? acc0b : acc0a;
                    float* p0c = (kt & 1) ? acc0d : acc0c;
                    mma_f16(p0a, A0[kt], bh[0], bh[1]); mma_f16(p0c, A0[kt], bh[2], bh[3]);
                    mma_f16(p0a, A0[kt], bl[0], bl[1]); mma_f16(p0c, A0[kt], bl[2], bl[3]);
                }
            }
        }

        // ---------------- gates -> warp-private scratch ----------------
        {
            const int r0 = gid, r1 = gid + 8;
            *(float2*)(gw + r0 * 18 + c0)     = make_float2(acc0a[0] + acc0b[0], acc0a[1] + acc0b[1]);
            *(float2*)(gw + r1 * 18 + c0)     = make_float2(acc0a[2] + acc0b[2], acc0a[3] + acc0b[3]);
            *(float2*)(gw + r0 * 18 + 8 + c0) = make_float2(acc0c[0] + acc0d[0], acc0c[1] + acc0d[1]);
            *(float2*)(gw + r1 * 18 + 8 + c0) = make_float2(acc0c[2] + acc0d[2], acc0c[3] + acc0d[3]);
            float* g1 = gw + 288;
            *(float2*)(g1 + r0 * 18 + c0)     = make_float2(acc1a[0] + acc1b[0], acc1a[1] + acc1b[1]);
            *(float2*)(g1 + r1 * 18 + c0)     = make_float2(acc1a[2] + acc1b[2], acc1a[3] + acc1b[3]);
            *(float2*)(g1 + r0 * 18 + 8 + c0) = make_float2(acc1c[0] + acc1d[0], acc1c[1] + acc1d[1]);
            *(float2*)(g1 + r1 * 18 + 8 + c0) = make_float2(acc1c[2] + acc1d[2], acc1c[3] + acc1d[3]);
        }
        __syncwarp(0xffffffffu);

        // ---------------- activations (warp-local) ----------------
        char* bwh = sm + SM_B + nb * 2 * BT;
        char* bwl = bwh + BT;
#pragma unroll
        for (int lay = 0; lay < 2; ++lay){
            if (lay == 0 ? (p >= TN) : (p < 1)) continue;
            const float* g = gw + lay * 288;
#pragma unroll
            for (int ui = 0; ui < 2; ++ui){
                const int up = ua + 2 * ui;
                const int u  = 4 * wrp + up;
                if (u >= HN) continue;
                const float gi = g[(4 * up + 0) * 18 + e] + bsr[lay * 8 + 0 + ui];
                const float gf = g[(4 * up + 1) * 18 + e] + bsr[lay * 8 + 2 + ui];
                const float gg = g[(4 * up + 2) * 18 + e] + bsr[lay * 8 + 4 + ui];
                const float go = g[(4 * up + 3) * 18 + e] + bsr[lay * 8 + 6 + ui];
                const float i_ = sigf(gi), f_ = sigf(gf);
                const float q_ = tanhx(gg), o_ = sigf(go);
                float& c = cc[lay * 2 + ui];
                c = fmaf(f_, c, i_ * q_);
                const float v = o_ * tanhx(c);
                if (lay == 1 && p == TN){
                    ((float*)(sm + SM_HEAD))[u * 16 + e] = v;   // final h1 stash
                } else {
                    const int col = lay ? (58 + u) : (8 + u);
                    const __half hv = __float2half_rn(v);
                    *(__half*)(bwh + e * BROW + col * 2) = hv;
                    *(__half*)(bwl + e * BROW + col * 2) =
                        __float2half_rn(v - __half2float(hv));
                }
            }
        }

        // ---------------- x staging: x(p+1) -> buf nb ----------------
        if (tid < 128 && (p + 1) < TN){
            const __half hv = __float2half_rn(xv);
            *(__half*)(bwh + xe * BROW + xd * 2) = hv;
            *(__half*)(bwl + xe * BROW + xd * 2) =
                __float2half_rn(xv - __half2float(hv));
            int tn = p + 2; if (tn > TN - 1) tn = TN - 1;
            xv = xgp[(size_t)tn * 8];
        }
    }

    __syncthreads();

    // ---- linear head on stashed final h1 ----
    if (tid < EN){
        const float* hd = (const float*)(sm + SM_HEAD);
        float acc = wl[HN];
#pragma unroll 10
        for (int j = 0; j < HN; ++j)
            acc = fmaf(hd[j * 16 + tid], wl[j], acc);
        out[cta * EN + tid] = acc;
    }
}

extern "C" void kernel_launch(void* const* d_in, const int* in_sizes, int n_in,
                              void* d_out, int out_size)
{
    const float* x    = (const float*)d_in[0];
    const float* Wih0 = (const float*)d_in[1];
    const float* Whh0 = (const float*)d_in[2];
    const float* bih0 = (const float*)d_in[3];
    const float* bhh0 = (const float*)d_in[4];
    const float* Wih1 = (const float*)d_in[5];
    const float* Whh1 = (const float*)d_in[6];
    const float* bih1 = (const float*)d_in[7];
    const float* bhh1 = (const float*)d_in[8];
    const float* Wlin = (const float*)d_in[9];
    const float* blin = (const float*)d_in[10];
    float* out = (float*)d_out;

    cudaFuncSetAttribute(lstm_mma4_kernel,
                         cudaFuncAttributeMaxDynamicSharedMemorySize, SMEM_BYTES);
    lstm_mma4_kernel<<<NCTA, NTHR, SMEM_BYTES>>>(
        x, Wih0, Whh0, bih0, bhh0, Wih1, Whh1, bih1, bhh1, Wlin, blin, out);
}

// round 11
// speedup vs baseline: 2.1685x; 1.2584x over previous
#include <cuda_runtime.h>
#include <cuda_fp16.h>
#include <cstdint>

typedef uint32_t u32;

#define HN 50
#define TN 512
#define EN 16
#define NCTA 128
#define NTHR 416   // 13 warps

#define BROW 272
#define BT   (16*BROW)        // 4352 one tile (16 rows x 272B), fp16 elems
// K layout in B tiles: cols 0-7 = x, 8-57 = h0, 58-107 = h1, 108-135 pad
#define SM_B     0            // [2 buf] = 2*4352 = 8704 (fp16 h, no lo tile)
#define SM_G     8704         // 13 warps * 2 lay * 16*18 f32 = 29952
#define SM_BIAS  38656        // [2][200] f32 = 1600
#define SM_WL    40256        // 51 f32 -> 256
#define SM_HEAD  40512        // [50][16] f32 = 3200
#define SMEM_BYTES 43712

__device__ __forceinline__ u32 smem_u32(const void* p){
    u32 a; asm("{ .reg .u64 t; cvta.to.shared.u64 t, %1; cvt.u32.u64 %0, t; }" : "=r"(a) : "l"(p));
    return a;
}
__device__ __forceinline__ u32 pk2h(__half a, __half b){
    return (u32)__half_as_ushort(a) | ((u32)__half_as_ushort(b) << 16);
}
__device__ __forceinline__ void mma_f16(float* c, const u32* a, u32 b0, u32 b1){
    asm volatile("mma.sync.aligned.m16n8k16.row.col.f32.f16.f16.f32 "
                 "{%0,%1,%2,%3}, {%4,%5,%6,%7}, {%8,%9}, {%0,%1,%2,%3};"
                 : "+f"(c[0]), "+f"(c[1]), "+f"(c[2]), "+f"(c[3])
                 : "r"(a[0]), "r"(a[1]), "r"(a[2]), "r"(a[3]), "r"(b0), "r"(b1));
}
__device__ __forceinline__ void ldsm4(u32* r, u32 addr){
    asm volatile("ldmatrix.sync.aligned.m8n8.x4.shared.b16 {%0,%1,%2,%3}, [%4];"
                 : "=r"(r[0]), "=r"(r[1]), "=r"(r[2]), "=r"(r[3]) : "r"(addr));
}
__device__ __forceinline__ float sigf(float v){
    return __fdividef(1.f, 1.f + __expf(-v));
}
__device__ __forceinline__ float tanhx(float v){
    return fmaf(2.f, __fdividef(1.f, 1.f + __expf(-2.f * v)), -1.f);
}

// interleaved A-row mapping: warp w, local r: unit u = 4w + (r>>2), gate t = r&3
__device__ __forceinline__ float a0elem_i(int w, int r, int k,
                                          const float* Whh0, const float* Wih0){
    const int u = 4*w + (r >> 2), t = r & 3;
    if (u >= HN) return 0.f;
    const int g = t * 50 + u;
    if (k < 8)  return Wih0[g * 8 + k];
    if (k < 58) return Whh0[g * 50 + (k - 8)];
    return 0.f;
}
__device__ __forceinline__ float a1elem_i(int w, int r, int k,
                                          const float* Wih1, const float* Whh1){
    const int u = 4*w + (r >> 2), t = r & 3;
    if (u >= HN) return 0.f;
    const int g = t * 50 + u;
    if (k >= 8  && k < 58)  return Wih1[g * 50 + (k - 8)];
    if (k >= 58 && k < 108) return Whh1[g * 50 + (k - 58)];
    return 0.f;
}

__global__ void __launch_bounds__(NTHR, 1)
lstm_mma5_kernel(const float* __restrict__ x,
                 const float* __restrict__ Wih0, const float* __restrict__ Whh0,
                 const float* __restrict__ bih0, const float* __restrict__ bhh0,
                 const float* __restrict__ Wih1, const float* __restrict__ Whh1,
                 const float* __restrict__ bih1, const float* __restrict__ bhh1,
                 const float* __restrict__ Wlin, const float* __restrict__ blin,
                 float* __restrict__ out)
{
    extern __shared__ char sm[];
    const u32 smb = smem_u32(sm);
    const int tid  = threadIdx.x;
    const int cta  = blockIdx.x;
    const int lane = tid & 31;
    const int wrp  = tid >> 5;

    float* bias = (float*)(sm + SM_BIAS);   // [2][200]
    float* wl   = (float*)(sm + SM_WL);

    // ---- init staging ----
    for (int i = tid; i < 200; i += NTHR){
        bias[i]       = bih0[i] + bhh0[i];
        bias[200 + i] = bih1[i] + bhh1[i];
    }
    if (tid < HN) wl[tid] = Wlin[tid];
    if (tid == HN) wl[HN] = blin[0];
    for (int i = tid; i < 2 * BT / 4; i += NTHR)
        ((u32*)(sm + SM_B))[i] = 0;

    // ---- register A fragments (fp16, unsplit W; interleaved rows) ----
    const int gid = lane >> 2;
    const int c0  = (lane & 3) * 2;
    u32 A0[4][4], A1[7][4];
#pragma unroll
    for (int kt = 0; kt < 4; ++kt)
#pragma unroll
        for (int q = 0; q < 4; ++q){
            const int r = gid + ((q & 1) ? 8 : 0);
            const int k = kt * 16 + c0 + ((q & 2) ? 8 : 0);
            A0[kt][q] = pk2h(__float2half_rn(a0elem_i(wrp, r, k,     Whh0, Wih0)),
                             __float2half_rn(a0elem_i(wrp, r, k + 1, Whh0, Wih0)));
        }
#pragma unroll
    for (int kt = 0; kt < 7; ++kt)
#pragma unroll
        for (int q = 0; q < 4; ++q){
            const int r = gid + ((q & 1) ? 8 : 0);
            const int k = kt * 16 + c0 + ((q & 2) ? 8 : 0);
            A1[kt][q] = pk2h(__float2half_rn(a1elem_i(wrp, r, k,     Wih1, Whh1)),
                             __float2half_rn(a1elem_i(wrp, r, k + 1, Wih1, Whh1)));
        }

    // ---- ldsm lane offsets (validated R7/R9 scheme) ----
    const int ln8 = lane & 7, grp = lane >> 3;
    const u32 bOffLane = (u32)((ln8 + ((grp >= 2) ? 8 : 0)) * BROW + ((grp & 1) ? 16 : 0));

    // ---- act roles: lane handles units {4w+ua, 4w+ua+2}, elem e ----
    const int e  = lane & 15;
    const int ua = lane >> 4;      // 0 or 1
    float* gw = (float*)(sm + SM_G) + wrp * 576;   // [2 lay][16 rows][18]

    // ---- x staging roles: tid<128 -> (xe, xd) ----
    const int xd = tid & 7, xe = tid >> 3;
    const float* xgp = (tid < 128) ? (x + ((size_t)(cta * EN + xe) * TN) * 8 + xd) : x;

    __syncthreads();   // staging visible

    // bias regs: bsr[lay*8 + t*2 + ui]
    float bsr[16];
#pragma unroll
    for (int lay = 0; lay < 2; ++lay)
#pragma unroll
        for (int t = 0; t < 4; ++t)
#pragma unroll
            for (int ui = 0; ui < 2; ++ui){
                const int u = 4 * wrp + ua + 2 * ui;
                bsr[lay * 8 + t * 2 + ui] = (u < HN) ? bias[lay * 200 + t * 50 + u] : 0.f;
            }

    // stage x(0) into buf0, prefetch x(1)
    float xv = 0.f;
    if (tid < 128){
        *(__half*)(sm + SM_B + xe * BROW + xd * 2) = __float2half_rn(xgp[0]);
        xv = xgp[8];
    }

    float cc[4] = {0.f, 0.f, 0.f, 0.f};   // [lay*2 + ui]

    // ================= phase loop (one barrier per phase) =================
    for (int p = 0; p <= TN; ++p){
        const int b = p & 1, nb = b ^ 1;

        __syncthreads();   // B[b] ready; B[nb] free

        // ---------------- MMA: single pass, fp16 ----------------
        float acc0a[4] = {0,0,0,0}, acc0b[4] = {0,0,0,0};
        float acc0c[4] = {0,0,0,0}, acc0d[4] = {0,0,0,0};
        float acc1a[4] = {0,0,0,0}, acc1b[4] = {0,0,0,0};
        float acc1c[4] = {0,0,0,0}, acc1d[4] = {0,0,0,0};
        {
            const u32 bhA = smb + SM_B + (u32)(b * BT) + bOffLane;
#pragma unroll
            for (int kt = 0; kt < 7; ++kt){
                u32 bh[4];
                ldsm4(bh, bhA + kt * 32);
                float* p1a = (kt & 1) ? acc1b : acc1a;   // split chains by kt parity
                float* p1c = (kt & 1) ? acc1d : acc1c;
                mma_f16(p1a, A1[kt], bh[0], bh[1]); mma_f16(p1c, A1[kt], bh[2], bh[3]);
                if (kt < 4){
                    float* p0a = (kt & 1) ? acc0b : acc0a;
                    float* p0c = (kt & 1) ? acc0d : acc0c;
                    mma_f16(p0a, A0[kt], bh[0], bh[1]); mma_f16(p0c, A0[kt], bh[2], bh[3]);
                }
            }
        }

        // ---------------- gates -> warp-private scratch ----------------
        {
            const int r0 = gid, r1 = gid + 8;
            *(float2*)(gw + r0 * 18 + c0)     = make_float2(acc0a[0] + acc0b[0], acc0a[1] + acc0b[1]);
            *(float2*)(gw + r1 * 18 + c0)     = make_float2(acc0a[2] + acc0b[2], acc0a[3] + acc0b[3]);
            *(float2*)(gw + r0 * 18 + 8 + c0) = make_float2(acc0c[0] + acc0d[0], acc0c[1] + acc0d[1]);
            *(float2*)(gw + r1 * 18 + 8 + c0) = make_float2(acc0c[2] + acc0d[2], acc0c[3] + acc0d[3]);
            float* g1 = gw + 288;
            *(float2*)(g1 + r0 * 18 + c0)     = make_float2(acc1a[0] + acc1b[0], acc1a[1] + acc1b[1]);
            *(float2*)(g1 + r1 * 18 + c0)     = make_float2(acc1a[2] + acc1b[2], acc1a[3] + acc1b[3]);
            *(float2*)(g1 + r0 * 18 + 8 + c0) = make_float2(acc1c[0] + acc1d[0], acc1c[1] + acc1d[1]);
            *(float2*)(g1 + r1 * 18 + 8 + c0) = make_float2(acc1c[2] + acc1d[2], acc1c[3] + acc1d[3]);
        }
        __syncwarp(0xffffffffu);

        // ---------------- activations (warp-local) ----------------
        char* bwh = sm + SM_B + nb * BT;
#pragma unroll
        for (int lay = 0; lay < 2; ++lay){
            if (lay == 0 ? (p >= TN) : (p < 1)) continue;
            const float* g = gw + lay * 288;
#pragma unroll
            for (int ui = 0; ui < 2; ++ui){
                const int up = ua + 2 * ui;
                const int u  = 4 * wrp + up;
                if (u >= HN) continue;
                const float gi = g[(4 * up + 0) * 18 + e] + bsr[lay * 8 + 0 + ui];
                const float gf = g[(4 * up + 1) * 18 + e] + bsr[lay * 8 + 2 + ui];
                const float gg = g[(4 * up + 2) * 18 + e] + bsr[lay * 8 + 4 + ui];
                const float go = g[(4 * up + 3) * 18 + e] + bsr[lay * 8 + 6 + ui];
                const float i_ = sigf(gi), f_ = sigf(gf);
                const float q_ = tanhx(gg), o_ = sigf(go);
                float& c = cc[lay * 2 + ui];
                c = fmaf(f_, c, i_ * q_);
                const float v = o_ * tanhx(c);
                if (lay == 1 && p == TN){
                    ((float*)(sm + SM_HEAD))[u * 16 + e] = v;   // final h1 stash
                } else {
                    const int col = lay ? (58 + u) : (8 + u);
                    *(__half*)(bwh + e * BROW + col * 2) = __float2half_rn(v);
                }
            }
        }

        // ---------------- x staging: x(p+1) -> buf nb ----------------
        if (tid < 128 && (p + 1) < TN){
            *(__half*)(bwh + xe * BROW + xd * 2) = __float2half_rn(xv);
            int tn = p + 2; if (tn > TN - 1) tn = TN - 1;
            xv = xgp[(size_t)tn * 8];
        }
    }

    __syncthreads();

    // ---- linear head on stashed final h1 ----
    if (tid < EN){
        const float* hd = (const float*)(sm + SM_HEAD);
        float acc = wl[HN];
#pragma unroll 10
        for (int j = 0; j < HN; ++j)
            acc = fmaf(hd[j * 16 + tid], wl[j], acc);
        out[cta * EN + tid] = acc;
    }
}

extern "C" void kernel_launch(void* const* d_in, const int* in_sizes, int n_in,
                              void* d_out, int out_size)
{
    const float* x    = (const float*)d_in[0];
    const float* Wih0 = (const float*)d_in[1];
    const float* Whh0 = (const float*)d_in[2];
    const float* bih0 = (const float*)d_in[3];
    const float* bhh0 = (const float*)d_in[4];
    const float* Wih1 = (const float*)d_in[5];
    const float* Whh1 = (const float*)d_in[6];
    const float* bih1 = (const float*)d_in[7];
    const float* bhh1 = (const float*)d_in[8];
    const float* Wlin = (const float*)d_in[9];
    const float* blin = (const float*)d_in[10];
    float* out = (float*)d_out;

    cudaFuncSetAttribute(lstm_mma5_kernel,
                         cudaFuncAttributeMaxDynamicSharedMemorySize, SMEM_BYTES);
    lstm_mma5_kernel<<<NCTA, NTHR, SMEM_BYTES>>>(
        x, Wih0, Whh0, bih0, bhh0, Wih1, Whh1, bih1, bhh1, Wlin, blin, out);
}

// round 12
// speedup vs baseline: 2.6814x; 1.2365x over previous
#include <cuda_runtime.h>
#include <cuda_fp16.h>
#include <cstdint>

typedef uint32_t u32;

#define HN 50
#define TN 512
#define EN 16
#define NCTA 128
#define NTHR 416   // 13 warps

#define BROW 272
#define BT   (16*BROW)        // 4352 one tile (16 rows x 272B), fp16 elems
// K layout in B tiles: cols 0-7 = x, 8-57 = h0, 58-107 = h1, 108-135 pad
#define SM_B     0            // [2 buf] = 2*4352 = 8704 (fp16 h)
#define SM_G     8704         // 13 warps * 2 lay * 16*18 f32 = 29952
#define SM_BIAS  38656        // [2][200] f32 = 1600
#define SM_WL    40256        // 51 f32 -> 256
#define SM_HEAD  40512        // [50][16] f32 = 3200
#define SMEM_BYTES 43712

__device__ __forceinline__ u32 smem_u32(const void* p){
    u32 a; asm("{ .reg .u64 t; cvta.to.shared.u64 t, %1; cvt.u32.u64 %0, t; }" : "=r"(a) : "l"(p));
    return a;
}
__device__ __forceinline__ u32 pk2h(__half a, __half b){
    return (u32)__half_as_ushort(a) | ((u32)__half_as_ushort(b) << 16);
}
__device__ __forceinline__ void mma_f16(float* c, const u32* a, u32 b0, u32 b1){
    asm volatile("mma.sync.aligned.m16n8k16.row.col.f32.f16.f16.f32 "
                 "{%0,%1,%2,%3}, {%4,%5,%6,%7}, {%8,%9}, {%0,%1,%2,%3};"
                 : "+f"(c[0]), "+f"(c[1]), "+f"(c[2]), "+f"(c[3])
                 : "r"(a[0]), "r"(a[1]), "r"(a[2]), "r"(a[3]), "r"(b0), "r"(b1));
}
__device__ __forceinline__ void ldsm4(u32* r, u32 addr){
    asm volatile("ldmatrix.sync.aligned.m8n8.x4.shared.b16 {%0,%1,%2,%3}, [%4];"
                 : "=r"(r[0]), "=r"(r[1]), "=r"(r[2]), "=r"(r[3]) : "r"(addr));
}
// ---- MUFU.TANH-based activations ----
__device__ __forceinline__ float tanha(float v){
    float r; asm("tanh.approx.f32 %0, %1;" : "=f"(r) : "f"(v)); return r;
}
__device__ __forceinline__ float siga(float v){
    return fmaf(0.5f, tanha(0.5f * v), 0.5f);
}

// interleaved A-row mapping: warp w, local r: unit u = 4w + (r>>2), gate t = r&3
__device__ __forceinline__ float a0elem_i(int w, int r, int k,
                                          const float* Whh0, const float* Wih0){
    const int u = 4*w + (r >> 2), t = r & 3;
    if (u >= HN) return 0.f;
    const int g = t * 50 + u;
    if (k < 8)  return Wih0[g * 8 + k];
    if (k < 58) return Whh0[g * 50 + (k - 8)];
    return 0.f;
}
__device__ __forceinline__ float a1elem_i(int w, int r, int k,
                                          const float* Wih1, const float* Whh1){
    const int u = 4*w + (r >> 2), t = r & 3;
    if (u >= HN) return 0.f;
    const int g = t * 50 + u;
    if (k >= 8  && k < 58)  return Wih1[g * 50 + (k - 8)];
    if (k >= 58 && k < 108) return Whh1[g * 50 + (k - 58)];
    return 0.f;
}

__global__ void __launch_bounds__(NTHR, 1)
lstm_mma6_kernel(const float* __restrict__ x,
                 const float* __restrict__ Wih0, const float* __restrict__ Whh0,
                 const float* __restrict__ bih0, const float* __restrict__ bhh0,
                 const float* __restrict__ Wih1, const float* __restrict__ Whh1,
                 const float* __restrict__ bih1, const float* __restrict__ bhh1,
                 const float* __restrict__ Wlin, const float* __restrict__ blin,
                 float* __restrict__ out)
{
    extern __shared__ char sm[];
    const u32 smb = smem_u32(sm);
    const int tid  = threadIdx.x;
    const int cta  = blockIdx.x;
    const int lane = tid & 31;
    const int wrp  = tid >> 5;

    float* bias = (float*)(sm + SM_BIAS);   // [2][200]
    float* wl   = (float*)(sm + SM_WL);

    // ---- init staging ----
    for (int i = tid; i < 200; i += NTHR){
        bias[i]       = bih0[i] + bhh0[i];
        bias[200 + i] = bih1[i] + bhh1[i];
    }
    if (tid < HN) wl[tid] = Wlin[tid];
    if (tid == HN) wl[HN] = blin[0];
    for (int i = tid; i < 2 * BT / 4; i += NTHR)
        ((u32*)(sm + SM_B))[i] = 0;

    // ---- register A fragments (fp16, unsplit W; interleaved rows) ----
    const int gid = lane >> 2;
    const int c0  = (lane & 3) * 2;
    u32 A0[4][4], A1[7][4];
#pragma unroll
    for (int kt = 0; kt < 4; ++kt)
#pragma unroll
        for (int q = 0; q < 4; ++q){
            const int r = gid + ((q & 1) ? 8 : 0);
            const int k = kt * 16 + c0 + ((q & 2) ? 8 : 0);
            A0[kt][q] = pk2h(__float2half_rn(a0elem_i(wrp, r, k,     Whh0, Wih0)),
                             __float2half_rn(a0elem_i(wrp, r, k + 1, Whh0, Wih0)));
        }
#pragma unroll
    for (int kt = 0; kt < 7; ++kt)
#pragma unroll
        for (int q = 0; q < 4; ++q){
            const int r = gid + ((q & 1) ? 8 : 0);
            const int k = kt * 16 + c0 + ((q & 2) ? 8 : 0);
            A1[kt][q] = pk2h(__float2half_rn(a1elem_i(wrp, r, k,     Wih1, Whh1)),
                             __float2half_rn(a1elem_i(wrp, r, k + 1, Wih1, Whh1)));
        }

    // ---- ldsm lane offsets (validated scheme) ----
    const int ln8 = lane & 7, grp = lane >> 3;
    const u32 bOffLane = (u32)((ln8 + ((grp >= 2) ? 8 : 0)) * BROW + ((grp & 1) ? 16 : 0));

    // ---- act roles: lane handles units {4w+ua, 4w+ua+2}, elem e ----
    const int e  = lane & 15;
    const int ua = lane >> 4;      // 0 or 1
    float* gw = (float*)(sm + SM_G) + wrp * 576;   // [2 lay][16 rows][18]

    // ---- x staging roles: tid<128 -> (xe, xd) ----
    const int xd = tid & 7, xe = tid >> 3;
    const float* xgp = (tid < 128) ? (x + ((size_t)(cta * EN + xe) * TN) * 8 + xd) : x;

    __syncthreads();   // staging visible

    // bias regs: bsr[lay*8 + t*2 + ui]
    float bsr[16];
#pragma unroll
    for (int lay = 0; lay < 2; ++lay)
#pragma unroll
        for (int t = 0; t < 4; ++t)
#pragma unroll
            for (int ui = 0; ui < 2; ++ui){
                const int u = 4 * wrp + ua + 2 * ui;
                bsr[lay * 8 + t * 2 + ui] = (u < HN) ? bias[lay * 200 + t * 50 + u] : 0.f;
            }

    // stage x(0) into buf0, prefetch x(1)
    float xv = 0.f;
    if (tid < 128){
        *(__half*)(sm + SM_B + xe * BROW + xd * 2) = __float2half_rn(xgp[0]);
        xv = xgp[8];
    }

    float cc[4] = {0.f, 0.f, 0.f, 0.f};   // [lay*2 + ui]

    // ================= phase loop (one barrier per phase) =================
    for (int p = 0; p <= TN; ++p){
        const int b = p & 1, nb = b ^ 1;

        __syncthreads();   // B[b] ready; B[nb] free

        // ---------------- MMA: single pass, fp16 ----------------
        float acc0a[4] = {0,0,0,0}, acc0b[4] = {0,0,0,0};
        float acc0c[4] = {0,0,0,0}, acc0d[4] = {0,0,0,0};
        float acc1a[4] = {0,0,0,0}, acc1b[4] = {0,0,0,0};
        float acc1c[4] = {0,0,0,0}, acc1d[4] = {0,0,0,0};
        {
            const u32 bhA = smb + SM_B + (u32)(b * BT) + bOffLane;
#pragma unroll
            for (int kt = 0; kt < 7; ++kt){
                u32 bh[4];
                ldsm4(bh, bhA + kt * 32);
                float* p1a = (kt & 1) ? acc1b : acc1a;   // split chains by kt parity
                float* p1c = (kt & 1) ? acc1d : acc1c;
                mma_f16(p1a, A1[kt], bh[0], bh[1]); mma_f16(p1c, A1[kt], bh[2], bh[3]);
                if (kt < 4){
                    float* p0a = (kt & 1) ? acc0b : acc0a;
                    float* p0c = (kt & 1) ? acc0d : acc0c;
                    mma_f16(p0a, A0[kt], bh[0], bh[1]); mma_f16(p0c, A0[kt], bh[2], bh[3]);
                }
            }
        }

        // ---------------- gates -> warp-private scratch ----------------
        {
            const int r0 = gid, r1 = gid + 8;
            *(float2*)(gw + r0 * 18 + c0)     = make_float2(acc0a[0] + acc0b[0], acc0a[1] + acc0b[1]);
            *(float2*)(gw + r1 * 18 + c0)     = make_float2(acc0a[2] + acc0b[2], acc0a[3] + acc0b[3]);
            *(float2*)(gw + r0 * 18 + 8 + c0) = make_float2(acc0c[0] + acc0d[0], acc0c[1] + acc0d[1]);
            *(float2*)(gw + r1 * 18 + 8 + c0) = make_float2(acc0c[2] + acc0d[2], acc0c[3] + acc0d[3]);
            float* g1 = gw + 288;
            *(float2*)(g1 + r0 * 18 + c0)     = make_float2(acc1a[0] + acc1b[0], acc1a[1] + acc1b[1]);
            *(float2*)(g1 + r1 * 18 + c0)     = make_float2(acc1a[2] + acc1b[2], acc1a[3] + acc1b[3]);
            *(float2*)(g1 + r0 * 18 + 8 + c0) = make_float2(acc1c[0] + acc1d[0], acc1c[1] + acc1d[1]);
            *(float2*)(g1 + r1 * 18 + 8 + c0) = make_float2(acc1c[2] + acc1d[2], acc1c[3] + acc1d[3]);
        }
        __syncwarp(0xffffffffu);

        // ---------------- activations (warp-local, MUFU.TANH) ----------------
        char* bwh = sm + SM_B + nb * BT;
#pragma unroll
        for (int lay = 0; lay < 2; ++lay){
            if (lay == 0 ? (p >= TN) : (p < 1)) continue;
            const float* g = gw + lay * 288;
#pragma unroll
            for (int ui = 0; ui < 2; ++ui){
                const int up = ua + 2 * ui;
                const int u  = 4 * wrp + up;
                if (u >= HN) continue;
                const float gi = g[(4 * up + 0) * 18 + e] + bsr[lay * 8 + 0 + ui];
                const float gf = g[(4 * up + 1) * 18 + e] + bsr[lay * 8 + 2 + ui];
                const float gg = g[(4 * up + 2) * 18 + e] + bsr[lay * 8 + 4 + ui];
                const float go = g[(4 * up + 3) * 18 + e] + bsr[lay * 8 + 6 + ui];
                const float i_ = siga(gi), f_ = siga(gf);
                const float q_ = tanha(gg), o_ = siga(go);
                float& c = cc[lay * 2 + ui];
                c = fmaf(f_, c, i_ * q_);
                const float v = o_ * tanha(c);
                if (lay == 1 && p == TN){
                    ((float*)(sm + SM_HEAD))[u * 16 + e] = v;   // final h1 stash
                } else {
                    const int col = lay ? (58 + u) : (8 + u);
                    *(__half*)(bwh + e * BROW + col * 2) = __float2half_rn(v);
                }
            }
        }

        // ---------------- x staging: x(p+1) -> buf nb ----------------
        if (tid < 128 && (p + 1) < TN){
            *(__half*)(bwh + xe * BROW + xd * 2) = __float2half_rn(xv);
            int tn = p + 2; if (tn > TN - 1) tn = TN - 1;
            xv = xgp[(size_t)tn * 8];
        }
    }

    __syncthreads();

    // ---- linear head on stashed final h1 ----
    if (tid < EN){
        const float* hd = (const float*)(sm + SM_HEAD);
        float acc = wl[HN];
#pragma unroll 10
        for (int j = 0; j < HN; ++j)
            acc = fmaf(hd[j * 16 + tid], wl[j], acc);
        out[cta * EN + tid] = acc;
    }
}

extern "C" void kernel_launch(void* const* d_in, const int* in_sizes, int n_in,
                              void* d_out, int out_size)
{
    const float* x    = (const float*)d_in[0];
    const float* Wih0 = (const float*)d_in[1];
    const float* Whh0 = (const float*)d_in[2];
    const float* bih0 = (const float*)d_in[3];
    const float* bhh0 = (const float*)d_in[4];
    const float* Wih1 = (const float*)d_in[5];
    const float* Whh1 = (const float*)d_in[6];
    const float* bih1 = (const float*)d_in[7];
    const float* bhh1 = (const float*)d_in[8];
    const float* Wlin = (const float*)d_in[9];
    const float* blin = (const float*)d_in[10];
    float* out = (float*)d_out;

    cudaFuncSetAttribute(lstm_mma6_kernel,
                         cudaFuncAttributeMaxDynamicSharedMemorySize, SMEM_BYTES);
    lstm_mma6_kernel<<<NCTA, NTHR, SMEM_BYTES>>>(
        x, Wih0, Whh0, bih0, bhh0, Wih1, Whh1, bih1, bhh1, Wlin, blin, out);
}

// round 13
// speedup vs baseline: 2.8644x; 1.0683x over previous
#include <cuda_runtime.h>
#include <cuda_fp16.h>
#include <cstdint>

typedef uint32_t u32;

#define HN 50
#define TN 512
#define EN 8            // batch elems per CTA
#define NCTA 256
#define NTHR 416        // 13 warps

#define BROW 272
#define BT   (8*BROW)         // 2176, one 8-row fp16 tile
// K layout in B tiles: cols 0-7 = x, 8-57 = h0, 58-107 = h1, 108-135 pad(0)
#define SM_B     0            // [2 buf] = 2*2176 = 4352
#define SM_G     4352         // 13 warps * 2 lay * 16 rows * 10 f32 = 16640
#define SM_BIAS  20992        // [2][200] f32 = 1600
#define SM_WL    22592        // 51 f32 -> 256
#define SM_HEAD  22848        // [50][8] f32 = 1600
#define SMEM_BYTES 24448

__device__ __forceinline__ u32 smem_u32(const void* p){
    u32 a; asm("{ .reg .u64 t; cvta.to.shared.u64 t, %1; cvt.u32.u64 %0, t; }" : "=r"(a) : "l"(p));
    return a;
}
__device__ __forceinline__ u32 pk2h(__half a, __half b){
    return (u32)__half_as_ushort(a) | ((u32)__half_as_ushort(b) << 16);
}
__device__ __forceinline__ void mma_f16(float* c, const u32* a, u32 b0, u32 b1){
    asm volatile("mma.sync.aligned.m16n8k16.row.col.f32.f16.f16.f32 "
                 "{%0,%1,%2,%3}, {%4,%5,%6,%7}, {%8,%9}, {%0,%1,%2,%3};"
                 : "+f"(c[0]), "+f"(c[1]), "+f"(c[2]), "+f"(c[3])
                 : "r"(a[0]), "r"(a[1]), "r"(a[2]), "r"(a[3]), "r"(b0), "r"(b1));
}
__device__ __forceinline__ void ldsm4(u32* r, u32 addr){
    asm volatile("ldmatrix.sync.aligned.m8n8.x4.shared.b16 {%0,%1,%2,%3}, [%4];"
                 : "=r"(r[0]), "=r"(r[1]), "=r"(r[2]), "=r"(r[3]) : "r"(addr));
}
// ---- MUFU.TANH-based activations ----
__device__ __forceinline__ float tanha(float v){
    float r; asm("tanh.approx.f32 %0, %1;" : "=f"(r) : "f"(v)); return r;
}
__device__ __forceinline__ float siga(float v){
    return fmaf(0.5f, tanha(0.5f * v), 0.5f);
}

// interleaved A-row mapping: warp w, local r: unit u = 4w + (r>>2), gate t = r&3
__device__ __forceinline__ float a0elem_i(int w, int r, int k,
                                          const float* Whh0, const float* Wih0){
    const int u = 4*w + (r >> 2), t = r & 3;
    if (u >= HN) return 0.f;
    const int g = t * 50 + u;
    if (k < 8)  return Wih0[g * 8 + k];
    if (k < 58) return Whh0[g * 50 + (k - 8)];
    return 0.f;
}
__device__ __forceinline__ float a1elem_i(int w, int r, int k,
                                          const float* Wih1, const float* Whh1){
    const int u = 4*w + (r >> 2), t = r & 3;
    if (u >= HN) return 0.f;
    const int g = t * 50 + u;
    if (k >= 8  && k < 58)  return Wih1[g * 50 + (k - 8)];
    if (k >= 58 && k < 108) return Whh1[g * 50 + (k - 58)];
    return 0.f;
}

__global__ void __launch_bounds__(NTHR, 2)
lstm_mma7_kernel(const float* __restrict__ x,
                 const float* __restrict__ Wih0, const float* __restrict__ Whh0,
                 const float* __restrict__ bih0, const float* __restrict__ bhh0,
                 const float* __restrict__ Wih1, const float* __restrict__ Whh1,
                 const float* __restrict__ bih1, const float* __restrict__ bhh1,
                 const float* __restrict__ Wlin, const float* __restrict__ blin,
                 float* __restrict__ out)
{
    extern __shared__ char sm[];
    const u32 smb = smem_u32(sm);
    const int tid  = threadIdx.x;
    const int cta  = blockIdx.x;
    const int lane = tid & 31;
    const int wrp  = tid >> 5;

    float* bias = (float*)(sm + SM_BIAS);   // [2][200]
    float* wl   = (float*)(sm + SM_WL);

    // ---- init staging ----
    for (int i = tid; i < 200; i += NTHR){
        bias[i]       = bih0[i] + bhh0[i];
        bias[200 + i] = bih1[i] + bhh1[i];
    }
    if (tid < HN) wl[tid] = Wlin[tid];
    if (tid == HN) wl[HN] = blin[0];
    for (int i = tid; i < 2 * BT / 4; i += NTHR)
        ((u32*)(sm + SM_B))[i] = 0;

    // ---- register A fragments (fp16; interleaved rows). kt=7 is all-zero pad ----
    const int gid = lane >> 2;
    const int c0  = (lane & 3) * 2;
    u32 A0[4][4], A1[7][4];
#pragma unroll
    for (int kt = 0; kt < 4; ++kt)
#pragma unroll
        for (int q = 0; q < 4; ++q){
            const int r = gid + ((q & 1) ? 8 : 0);
            const int k = kt * 16 + c0 + ((q & 2) ? 8 : 0);
            A0[kt][q] = pk2h(__float2half_rn(a0elem_i(wrp, r, k,     Whh0, Wih0)),
                             __float2half_rn(a0elem_i(wrp, r, k + 1, Whh0, Wih0)));
        }
#pragma unroll
    for (int kt = 0; kt < 7; ++kt)
#pragma unroll
        for (int q = 0; q < 4; ++q){
            const int r = gid + ((q & 1) ? 8 : 0);
            const int k = kt * 16 + c0 + ((q & 2) ? 8 : 0);
            A1[kt][q] = pk2h(__float2half_rn(a1elem_i(wrp, r, k,     Wih1, Whh1)),
                             __float2half_rn(a1elem_i(wrp, r, k + 1, Wih1, Whh1)));
        }

    // ---- ldsm lane offsets: x4 covers TWO kt per issue ----
    // group g = lane>>3: matrices (kt_pair: g>>1) at col 16B offsets; rows 0-7 = ln8
    const int ln8 = lane & 7, grp = lane >> 3;
    const u32 bOffLane = (u32)(ln8 * BROW + (grp & 1) * 16 + (grp >> 1) * 32);

    // ---- act roles: lane = up*8 + e  (up = unit-in-warp 0..3, e = elem 0..7) ----
    const int e  = lane & 7;
    const int up = lane >> 3;
    const int au = 4 * wrp + up;           // unit (valid if < 50)
    float* gw = (float*)(sm + SM_G) + wrp * 320;   // [2 lay][16 rows][10]

    // ---- x staging roles: tid<64 -> (xe, xd) ----
    const int xd = tid & 7, xe = tid >> 3;
    const float* xgp = (tid < 64) ? (x + ((size_t)(cta * EN + xe) * TN) * 8 + xd) : x;

    __syncthreads();   // staging visible

    // bias regs: bsr[lay*4 + t] for unit au
    float bsr[8];
#pragma unroll
    for (int lay = 0; lay < 2; ++lay)
#pragma unroll
        for (int t = 0; t < 4; ++t)
            bsr[lay * 4 + t] = (au < HN) ? bias[lay * 200 + t * 50 + au] : 0.f;

    // stage x(0) into buf0, prefetch x(1)
    float xv = 0.f;
    if (tid < 64){
        *(__half*)(sm + SM_B + xe * BROW + xd * 2) = __float2half_rn(xgp[0]);
        xv = xgp[8];
    }

    float cc0 = 0.f, cc1 = 0.f;

    // ================= phase loop (one barrier per phase) =================
    for (int p = 0; p <= TN; ++p){
        const int b = p & 1, nb = b ^ 1;

        __syncthreads();   // B[b] ready; B[nb] free

        // ---------------- MMA: single pass fp16, N=8 ----------------
        float acc0[4] = {0,0,0,0};
        float acc1[4] = {0,0,0,0};
        {
            const u32 bhA = smb + SM_B + (u32)(b * BT) + bOffLane;
#pragma unroll
            for (int i = 0; i < 4; ++i){       // kt pair {2i, 2i+1}
                u32 bh[4];
                ldsm4(bh, bhA + i * 64);
                const int k0 = 2 * i, k1 = 2 * i + 1;
                mma_f16(acc1, A1[k0], bh[0], bh[1]);
                if (k1 < 7) mma_f16(acc1, A1[k1], bh[2], bh[3]);
                if (k0 < 4) mma_f16(acc0, A0[k0], bh[0], bh[1]);
                if (k1 < 4) mma_f16(acc0, A0[k1], bh[2], bh[3]);
            }
        }

        // ---------------- gates -> warp-private scratch ----------------
        {
            const int r0 = gid, r1 = gid + 8;
            *(float2*)(gw + r0 * 10 + c0)       = make_float2(acc0[0], acc0[1]);
            *(float2*)(gw + r1 * 10 + c0)       = make_float2(acc0[2], acc0[3]);
            *(float2*)(gw + 160 + r0 * 10 + c0) = make_float2(acc1[0], acc1[1]);
            *(float2*)(gw + 160 + r1 * 10 + c0) = make_float2(acc1[2], acc1[3]);
        }
        __syncwarp(0xffffffffu);

        // ---------------- activations (warp-local, MUFU.TANH) ----------------
        char* bwh = sm + SM_B + nb * BT;
        if (au < HN){
#pragma unroll
            for (int lay = 0; lay < 2; ++lay){
                if (lay == 0 ? (p >= TN) : (p < 1)) continue;
                const float* g = gw + lay * 160;
                const float gi = g[(4 * up + 0) * 10 + e] + bsr[lay * 4 + 0];
                const float gf = g[(4 * up + 1) * 10 + e] + bsr[lay * 4 + 1];
                const float gg = g[(4 * up + 2) * 10 + e] + bsr[lay * 4 + 2];
                const float go = g[(4 * up + 3) * 10 + e] + bsr[lay * 4 + 3];
                const float i_ = siga(gi), f_ = siga(gf);
                const float q_ = tanha(gg), o_ = siga(go);
                float& c = lay ? cc1 : cc0;
                c = fmaf(f_, c, i_ * q_);
                const float v = o_ * tanha(c);
                if (lay == 1 && p == TN){
                    ((float*)(sm + SM_HEAD))[au * 8 + e] = v;   // final h1 stash
                } else {
                    const int col = lay ? (58 + au) : (8 + au);
                    *(__half*)(bwh + e * BROW + col * 2) = __float2half_rn(v);
                }
            }
        }

        // ---------------- x staging: x(p+1) -> buf nb ----------------
        if (tid < 64 && (p + 1) < TN){
            *(__half*)(bwh + xe * BROW + xd * 2) = __float2half_rn(xv);
            int tn = p + 2; if (tn > TN - 1) tn = TN - 1;
            xv = xgp[(size_t)tn * 8];
        }
    }

    __syncthreads();

    // ---- linear head on stashed final h1 ----
    if (tid < EN){
        const float* hd = (const float*)(sm + SM_HEAD);
        float acc = wl[HN];
#pragma unroll 10
        for (int j = 0; j < HN; ++j)
            acc = fmaf(hd[j * 8 + tid], wl[j], acc);
        out[cta * EN + tid] = acc;
    }
}

extern "C" void kernel_launch(void* const* d_in, const int* in_sizes, int n_in,
                              void* d_out, int out_size)
{
    const float* x    = (const float*)d_in[0];
    const float* Wih0 = (const float*)d_in[1];
    const float* Whh0 = (const float*)d_in[2];
    const float* bih0 = (const float*)d_in[3];
    const float* bhh0 = (const float*)d_in[4];
    const float* Wih1 = (const float*)d_in[5];
    const float* Whh1 = (const float*)d_in[6];
    const float* bih1 = (const float*)d_in[7];
    const float* bhh1 = (const float*)d_in[8];
    const float* Wlin = (const float*)d_in[9];
    const float* blin = (const float*)d_in[10];
    float* out = (float*)d_out;

    cudaFuncSetAttribute(lstm_mma7_kernel,
                         cudaFuncAttributeMaxDynamicSharedMemorySize, SMEM_BYTES);
    lstm_mma7_kernel<<<NCTA, NTHR, SMEM_BYTES>>>(
        x, Wih0, Whh0, bih0, bhh0, Wih1, Whh1, bih1, bhh1, Wlin, blin, out);
}

// round 14
// speedup vs baseline: 3.0343x; 1.0593x over previous
#include <cuda_runtime.h>
#include <cuda_fp16.h>
#include <cstdint>

typedef uint32_t u32;

#define HN 50
#define TN 512
#define EN 8            // batch elems per CTA
#define NCTA 256
#define NTHR 224        // 7 warps, M=32 per warp

#define BROW 272
#define BT   (8*BROW)         // 2176, one 8-row fp16 tile
// K layout in B tiles: 0-7 = x, 8-57 = h0, 58 = const 1.0 (bias col),
//                      59-108 = h1, 109-135 pad(0)
#define SM_B     0            // [2 buf] = 4352
#define SM_G     4352         // 7 warps * 2 lay * 32 rows * 10 f32 = 17920
#define SM_WL    22272        // 51 f32 -> 256
#define SM_HEAD  22528        // [50][8] f32 = 1600
#define SMEM_BYTES 24128

__device__ __forceinline__ u32 smem_u32(const void* p){
    u32 a; asm("{ .reg .u64 t; cvta.to.shared.u64 t, %1; cvt.u32.u64 %0, t; }" : "=r"(a) : "l"(p));
    return a;
}
__device__ __forceinline__ u32 pk2h(__half a, __half b){
    return (u32)__half_as_ushort(a) | ((u32)__half_as_ushort(b) << 16);
}
__device__ __forceinline__ void mma_f16(float* c, const u32* a, u32 b0, u32 b1){
    asm volatile("mma.sync.aligned.m16n8k16.row.col.f32.f16.f16.f32 "
                 "{%0,%1,%2,%3}, {%4,%5,%6,%7}, {%8,%9}, {%0,%1,%2,%3};"
                 : "+f"(c[0]), "+f"(c[1]), "+f"(c[2]), "+f"(c[3])
                 : "r"(a[0]), "r"(a[1]), "r"(a[2]), "r"(a[3]), "r"(b0), "r"(b1));
}
__device__ __forceinline__ void ldsm4(u32* r, u32 addr){
    asm volatile("ldmatrix.sync.aligned.m8n8.x4.shared.b16 {%0,%1,%2,%3}, [%4];"
                 : "=r"(r[0]), "=r"(r[1]), "=r"(r[2]), "=r"(r[3]) : "r"(addr));
}
__device__ __forceinline__ float tanha(float v){
    float r; asm("tanh.approx.f32 %0, %1;" : "=f"(r) : "f"(v)); return r;
}
__device__ __forceinline__ float siga(float v){
    return fmaf(0.5f, tanha(0.5f * v), 0.5f);
}

// A element (bias folded at k=58). g = gate-major row t*50+u.
__device__ __forceinline__ float a0elem(int u, int t, int k,
                                        const float* Whh0, const float* Wih0,
                                        const float* bih0, const float* bhh0){
    if (u >= HN) return 0.f;
    const int g = t * 50 + u;
    if (k < 8)   return Wih0[g * 8 + k];
    if (k < 58)  return Whh0[g * 50 + (k - 8)];
    if (k == 58) return bih0[g] + bhh0[g];
    return 0.f;
}
__device__ __forceinline__ float a1elem(int u, int t, int k,
                                        const float* Wih1, const float* Whh1,
                                        const float* bih1, const float* bhh1){
    if (u >= HN) return 0.f;
    const int g = t * 50 + u;
    if (k >= 8 && k < 58)   return Wih1[g * 50 + (k - 8)];
    if (k == 58)            return bih1[g] + bhh1[g];
    if (k >= 59 && k < 109) return Whh1[g * 50 + (k - 59)];
    return 0.f;
}

__global__ void __launch_bounds__(NTHR, 2)
lstm_mma8_kernel(const float* __restrict__ x,
                 const float* __restrict__ Wih0, const float* __restrict__ Whh0,
                 const float* __restrict__ bih0, const float* __restrict__ bhh0,
                 const float* __restrict__ Wih1, const float* __restrict__ Whh1,
                 const float* __restrict__ bih1, const float* __restrict__ bhh1,
                 const float* __restrict__ Wlin, const float* __restrict__ blin,
                 float* __restrict__ out)
{
    extern __shared__ char sm[];
    const u32 smb = smem_u32(sm);
    const int tid  = threadIdx.x;
    const int cta  = blockIdx.x;
    const int lane = tid & 31;
    const int wrp  = tid >> 5;           // 0..6

    float* wl = (float*)(sm + SM_WL);

    // ---- init staging ----
    if (tid < HN) wl[tid] = Wlin[tid];
    if (tid == HN) wl[HN] = blin[0];
    for (int i = tid; i < 2 * BT / 4; i += NTHR)
        ((u32*)(sm + SM_B))[i] = 0;

    // ---- register A fragments: 2 M16 tiles per warp (rows = units 8w+4tt+(r>>2), gate r&3) ----
    const int gid = lane >> 2;
    const int c0  = (lane & 3) * 2;
    u32 A0[2][4][4], A1[2][7][4];
#pragma unroll
    for (int tt = 0; tt < 2; ++tt){
#pragma unroll
        for (int kt = 0; kt < 7; ++kt)
#pragma unroll
            for (int q = 0; q < 4; ++q){
                const int r = gid + ((q & 1) ? 8 : 0);
                const int k = kt * 16 + c0 + ((q & 2) ? 8 : 0);
                const int u = 8 * wrp + 4 * tt + (r >> 2);
                const int t = r & 3;
                A1[tt][kt][q] = pk2h(__float2half_rn(a1elem(u, t, k,     Wih1, Whh1, bih1, bhh1)),
                                     __float2half_rn(a1elem(u, t, k + 1, Wih1, Whh1, bih1, bhh1)));
                if (kt < 4)
                    A0[tt][kt][q] = pk2h(__float2half_rn(a0elem(u, t, k,     Whh0, Wih0, bih0, bhh0)),
                                         __float2half_rn(a0elem(u, t, k + 1, Whh0, Wih0, bih0, bhh0)));
            }
    }

    // ---- ldsm lane offsets: x4 covers kt pair {2i, 2i+1} ----
    const int ln8 = lane & 7, grp = lane >> 3;
    const u32 bOffLane = (u32)(ln8 * BROW + (grp & 1) * 16 + (grp >> 1) * 32);

    // ---- act roles: lane = us*8 + e ----
    const int e  = lane & 7;
    const int us = lane >> 3;              // 0..3
    float* gw = (float*)(sm + SM_G) + wrp * 640;   // [2 lay][32 rows][10]

    // ---- x staging roles: tid<64 -> (xe, xd) ----
    const int xd = tid & 7, xe = tid >> 3;
    const float* xgp = (tid < 64) ? (x + ((size_t)(cta * EN + xe) * TN) * 8 + xd) : x;

    // const-1 bias column in both buffers (col 58), after zeroing, before use
    __syncthreads();
    if (tid < 16){
        const int bb = tid >> 3, ee = tid & 7;
        *(__half*)(sm + SM_B + bb * BT + ee * BROW + 58 * 2) = __float2half_rn(1.f);
    }

    // stage x(0) into buf0, prefetch x(1)
    float xv = 0.f;
    if (tid < 64){
        *(__half*)(sm + SM_B + xe * BROW + xd * 2) = __float2half_rn(xgp[0]);
        xv = xgp[8];
    }

    float cc[4] = {0.f, 0.f, 0.f, 0.f};   // [lay*2 + tt]

    // ================= phase loop (one barrier per phase) =================
    for (int p = 0; p <= TN; ++p){
        const int b = p & 1, nb = b ^ 1;

        __syncthreads();   // B[b] ready; B[nb] free

        // ---------------- MMA: single pass fp16, N=8, 2 M-tiles ----------------
        float acc0[2][4] = {{0,0,0,0},{0,0,0,0}};
        float acc1[2][4] = {{0,0,0,0},{0,0,0,0}};
        {
            const u32 bhA = smb + SM_B + (u32)(b * BT) + bOffLane;
#pragma unroll
            for (int i = 0; i < 4; ++i){       // kt pair {2i, 2i+1}
                u32 bh[4];
                ldsm4(bh, bhA + i * 64);
                const int k0 = 2 * i, k1 = 2 * i + 1;
#pragma unroll
                for (int tt = 0; tt < 2; ++tt){
                    mma_f16(acc1[tt], A1[tt][k0], bh[0], bh[1]);
                    if (k1 < 7) mma_f16(acc1[tt], A1[tt][k1], bh[2], bh[3]);
                    if (k0 < 4) mma_f16(acc0[tt], A0[tt][k0], bh[0], bh[1]);
                    if (k1 < 4) mma_f16(acc0[tt], A0[tt][k1], bh[2], bh[3]);
                }
            }
        }

        // ---------------- gates -> warp-private scratch ----------------
        {
#pragma unroll
            for (int tt = 0; tt < 2; ++tt){
                const int r0 = tt * 16 + gid, r1 = r0 + 8;
                *(float2*)(gw + r0 * 10 + c0)       = make_float2(acc0[tt][0], acc0[tt][1]);
                *(float2*)(gw + r1 * 10 + c0)       = make_float2(acc0[tt][2], acc0[tt][3]);
                *(float2*)(gw + 320 + r0 * 10 + c0) = make_float2(acc1[tt][0], acc1[tt][1]);
                *(float2*)(gw + 320 + r1 * 10 + c0) = make_float2(acc1[tt][2], acc1[tt][3]);
            }
        }
        __syncwarp(0xffffffffu);

        // ---------------- activations (warp-local, MUFU.TANH, bias pre-folded) ----------------
        char* bwh = sm + SM_B + nb * BT;
#pragma unroll
        for (int lay = 0; lay < 2; ++lay){
            if (lay == 0 ? (p >= TN) : (p < 1)) continue;
            const float* g = gw + lay * 320;
#pragma unroll
            for (int tt = 0; tt < 2; ++tt){
                const int au = 8 * wrp + 4 * tt + us;
                if (au >= HN) continue;
                const int rb = tt * 16 + 4 * us;
                const float gi = g[(rb + 0) * 10 + e];
                const float gf = g[(rb + 1) * 10 + e];
                const float gg = g[(rb + 2) * 10 + e];
                const float go = g[(rb + 3) * 10 + e];
                const float i_ = siga(gi), f_ = siga(gf);
                const float q_ = tanha(gg), o_ = siga(go);
                float& c = cc[lay * 2 + tt];
                c = fmaf(f_, c, i_ * q_);
                const float v = o_ * tanha(c);
                if (lay == 1 && p == TN){
                    ((float*)(sm + SM_HEAD))[au * 8 + e] = v;   // final h1 stash
                } else {
                    const int col = lay ? (59 + au) : (8 + au);
                    *(__half*)(bwh + e * BROW + col * 2) = __float2half_rn(v);
                }
            }
        }

        // ---------------- x staging: x(p+1) -> buf nb ----------------
        if (tid < 64 && (p + 1) < TN){
            *(__half*)(bwh + xe * BROW + xd * 2) = __float2half_rn(xv);
            int tn = p + 2; if (tn > TN - 1) tn = TN - 1;
            xv = xgp[(size_t)tn * 8];
        }
    }

    __syncthreads();

    // ---- linear head on stashed final h1 ----
    if (tid < EN){
        const float* hd = (const float*)(sm + SM_HEAD);
        float acc = wl[HN];
#pragma unroll 10
        for (int j = 0; j < HN; ++j)
            acc = fmaf(hd[j * 8 + tid], wl[j], acc);
        out[cta * EN + tid] = acc;
    }
}

extern "C" void kernel_launch(void* const* d_in, const int* in_sizes, int n_in,
                              void* d_out, int out_size)
{
    const float* x    = (const float*)d_in[0];
    const float* Wih0 = (const float*)d_in[1];
    const float* Whh0 = (const float*)d_in[2];
    const float* bih0 = (const float*)d_in[3];
    const float* bhh0 = (const float*)d_in[4];
    const float* Wih1 = (const float*)d_in[5];
    const float* Whh1 = (const float*)d_in[6];
    const float* bih1 = (const float*)d_in[7];
    const float* bhh1 = (const float*)d_in[8];
    const float* Wlin = (const float*)d_in[9];
    const float* blin = (const float*)d_in[10];
    float* out = (float*)d_out;

    cudaFuncSetAttribute(lstm_mma8_kernel,
                         cudaFuncAttributeMaxDynamicSharedMemorySize, SMEM_BYTES);
    lstm_mma8_kernel<<<NCTA, NTHR, SMEM_BYTES>>>(
        x, Wih0, Whh0, bih0, bhh0, Wih1, Whh1, bih1, bhh1, Wlin, blin, out);
}